// round 15
// baseline (speedup 1.0000x reference)
#include <cuda_runtime.h>
#include <cuda_bf16.h>
#include <cstdint>

// ---------------- problem dims ----------------
#define SEQ    32
#define BATCH  32
#define SB     1024          // SEQ*BATCH
#define HID    512
#define H3     1536
#define DIN    512
#define VOCAB  32000
#define FEA    50

// ---------------- scratch (static device, no allocs) ----------------
__device__ __align__(16) __nv_bfloat16 g_embBf [SB * DIN];
__device__ __align__(16) __nv_bfloat16 g_Wih0Bf[H3 * DIN];
__device__ __align__(16) __nv_bfloat16 g_Wih1Bf[H3 * HID];
__device__ __align__(16) __nv_bfloat16 g_WooBf [HID * HID];
__device__ __align__(16) __nv_bfloat16 g_WoutBf[(size_t)VOCAB * HID];
__device__ __align__(16) float g_gi     [SB * H3];
__device__ __align__(16) __nv_bfloat16 g_h0Bf [SB * HID];
__device__ __align__(16) float g_outseq [SB * HID];
__device__ __align__(16) __nv_bfloat16 g_outBf[SB * HID];
__device__ __align__(16) __nv_bfloat16 g_actBf[SB * HID];
__device__ __align__(16) __nv_bfloat16 g_logitsBf[(size_t)SB * VOCAB];  // 65 MB
__device__ float g_fg[SB], g_rg[SB];
__device__ float g_fs[SB * 16];
__device__ float g_scoreout[BATCH * HID];
__device__ float g_energy[BATCH * FEA * 80];
__device__ float g_fattn[SB * FEA];
__device__ float g_rowsum[SB];

__device__ __forceinline__ float sigm(float x) { return 1.f / (1.f + expf(-x)); }

// packed dual-fp32 FMA (Blackwell f32x2 pipe; PTX-only form)
__device__ __forceinline__ unsigned long long fma2(unsigned long long a,
                                                   unsigned long long b,
                                                   unsigned long long c) {
    unsigned long long d;
    asm("fma.rn.f32x2 %0,%1,%2,%3;" : "=l"(d) : "l"(a), "l"(b), "l"(c));
    return d;
}
__device__ __forceinline__ float hsum2(unsigned long long v) {
    uint32_t lo, hi;
    asm("mov.b64 {%0,%1},%2;" : "=r"(lo), "=r"(hi) : "l"(v));
    return __uint_as_float(lo) + __uint_as_float(hi);
}
// bf16x2 (packed in u32) -> f32x2 (packed in u64)
__device__ __forceinline__ unsigned long long bf2f2(uint32_t v) {
    uint32_t lo = v << 16;
    uint32_t hi = v & 0xFFFF0000u;
    unsigned long long d;
    asm("mov.b64 %0,{%1,%2};" : "=l"(d) : "r"(lo), "r"(hi));
    return d;
}

// ---------------- HMMA bf16 GEMM: C[M,N] = A[M,K] @ B[N,K]^T + bias[N] ----
// BM=128: 512 thr, 16 warps (4m x 4n), warp tile 32x32, acc 32 regs (NO spills).
// BM=64:  256 thr, 8 warps (1m x 8n), warp tile 64x16.
// 4-stage cp.async pipeline, 1 __syncthreads per K-chunk.
// smem rows of 32 bf16 (64B), chunk-XOR swizzle (conflict-free ldmatrix+fill).
// Cbf!=null -> bf16 out; RG!=null -> tanh(acc+bias+rg*so) bf16 out.
#define BK 32

__device__ __forceinline__ uint32_t sw_off(int row, int chunk) {
    return (uint32_t)(row * 64 + ((chunk ^ ((row >> 1) & 3)) << 4));
}

template<int BM>
__global__ __launch_bounds__(512) void gemm_hmma(
    const __nv_bfloat16* __restrict__ A, const __nv_bfloat16* __restrict__ B,
    const float* __restrict__ bias, float* __restrict__ C,
    __nv_bfloat16* __restrict__ Cbf,
    const float* __restrict__ RG, const float* __restrict__ SO,
    int N, int K)
{
    constexpr int ASZ = BM * 64;         // A stage bytes
    constexpr int BSZ = 128 * 64;        // B stage bytes
    constexpr int SST = ASZ + BSZ;       // stage stride
    constexpr int MI  = (BM == 128) ? 2 : 4;   // m16 tiles per warp
    constexpr int NI  = (BM == 128) ? 4 : 2;   // n8 tiles per warp
    extern __shared__ __align__(128) char gsm[];
    const int bm = blockIdx.y * BM, bn = blockIdx.x * 128;
    const int tid = threadIdx.x;
    const int warp = tid >> 5, lane = tid & 31;
    const int wm = (BM == 128) ? (warp & 3) * 32 : 0;
    const int wn = (BM == 128) ? (warp >> 2) * 32 : warp * 16;

    const uint32_t sBase = (uint32_t)__cvta_generic_to_shared(gsm);
    const int nk = K / BK;

    float acc[MI][NI][4];
#pragma unroll
    for (int i = 0; i < MI; i++)
#pragma unroll
        for (int j = 0; j < NI; j++)
#pragma unroll
            for (int k = 0; k < 4; k++) acc[i][j][k] = 0.f;

    const int fr = tid >> 2, fc = tid & 3;
    auto issue = [&](int st, int kc) {
        if (kc < nk) {
            const __nv_bfloat16* Ag = A + (size_t)(bm + fr) * K + kc * BK + fc * 8;
            const __nv_bfloat16* Bg = B + (size_t)(bn + fr) * K + kc * BK + fc * 8;
            uint32_t aB = sBase + (uint32_t)(st * SST);
            uint32_t bB = aB + ASZ;
            asm volatile("cp.async.cg.shared.global [%0],[%1],16;"
                         :: "r"(aB + sw_off(fr, fc)), "l"(Ag));
            asm volatile("cp.async.cg.shared.global [%0],[%1],16;"
                         :: "r"(bB + sw_off(fr, fc)), "l"(Bg));
            if (BM == 64)   // 256 thr: B needs second line
                asm volatile("cp.async.cg.shared.global [%0],[%1],16;"
                             :: "r"(bB + sw_off(fr + 64, fc)), "l"(Bg + (size_t)64 * K));
        }
        asm volatile("cp.async.commit_group;");
    };

    issue(0, 0); issue(1, 1); issue(2, 2);

    for (int kt = 0; kt < nk; kt++) {
        const int cur = kt & 3;
        asm volatile("cp.async.wait_group 2;");
        __syncthreads();
        issue((kt + 3) & 3, kt + 3);
        const uint32_t aC = sBase + (uint32_t)(cur * SST);
        const uint32_t bC = aC + ASZ;
#pragma unroll
        for (int kk = 0; kk < 2; kk++) {
            const int kb = kk * 2;
            uint32_t a[MI][4], b[NI][2];
#pragma unroll
            for (int mi = 0; mi < MI; mi++) {
                int row = wm + mi * 16 + (lane & 15);
                uint32_t addr = aC + sw_off(row, kb + (lane >> 4));
                asm volatile("ldmatrix.sync.aligned.m8n8.x4.shared.b16 {%0,%1,%2,%3}, [%4];"
                             : "=r"(a[mi][0]), "=r"(a[mi][1]), "=r"(a[mi][2]), "=r"(a[mi][3])
                             : "r"(addr));
            }
#pragma unroll
            for (int ni = 0; ni < NI; ni++) {
                int row = wn + ni * 8 + (lane & 7);
                uint32_t addr = bC + sw_off(row, kb + ((lane >> 3) & 1));
                asm volatile("ldmatrix.sync.aligned.m8n8.x2.shared.b16 {%0,%1}, [%2];"
                             : "=r"(b[ni][0]), "=r"(b[ni][1]) : "r"(addr));
            }
#pragma unroll
            for (int mi = 0; mi < MI; mi++)
#pragma unroll
                for (int ni = 0; ni < NI; ni++) {
                    asm volatile(
                        "mma.sync.aligned.m16n8k16.row.col.f32.bf16.bf16.f32 "
                        "{%0,%1,%2,%3},{%4,%5,%6,%7},{%8,%9},{%0,%1,%2,%3};\n"
                        : "+f"(acc[mi][ni][0]), "+f"(acc[mi][ni][1]),
                          "+f"(acc[mi][ni][2]), "+f"(acc[mi][ni][3])
                        : "r"(a[mi][0]), "r"(a[mi][1]), "r"(a[mi][2]), "r"(a[mi][3]),
                          "r"(b[ni][0]), "r"(b[ni][1]));
                }
        }
    }

    const int g = lane >> 2, tg = lane & 3;
#pragma unroll
    for (int mi = 0; mi < MI; mi++)
#pragma unroll
        for (int ni = 0; ni < NI; ni++) {
            int row = bm + wm + mi * 16 + g;
            int col = bn + wn + ni * 8 + tg * 2;
            float b0 = bias[col], b1 = bias[col + 1];
            float v0 = acc[mi][ni][0] + b0, v1 = acc[mi][ni][1] + b1;
            float v2 = acc[mi][ni][2] + b0, v3 = acc[mi][ni][3] + b1;
            if (RG) {
                int ba = row & 31, bb = (row + 8) & 31;
                float r0 = RG[row], r1 = RG[row + 8];
                v0 = tanhf(v0 + r0 * SO[ba * HID + col]);
                v1 = tanhf(v1 + r0 * SO[ba * HID + col + 1]);
                v2 = tanhf(v2 + r1 * SO[bb * HID + col]);
                v3 = tanhf(v3 + r1 * SO[bb * HID + col + 1]);
            }
            if (Cbf) {
                *(__nv_bfloat162*)&Cbf[(size_t)row * N + col] = __floats2bfloat162_rn(v0, v1);
                *(__nv_bfloat162*)&Cbf[(size_t)(row + 8) * N + col] = __floats2bfloat162_rn(v2, v3);
            } else {
                C[(size_t)row * N + col]           = v0;
                C[(size_t)row * N + col + 1]       = v1;
                C[(size_t)(row + 8) * N + col]     = v2;
                C[(size_t)(row + 8) * N + col + 1] = v3;
            }
        }
}

// ---------------- GRU v6: cluster-of-8, smem weights, 768 thr --------------
// 128 CTAs x 768 threads, clusters of 8. Cluster = one batch-pair.
// CTA rank = u-slice (64 units x 3 gates = 192 rows, 196KB bf16 in smem).
// Thread (g, kh): g = t%48 -> rows 4g..4g+3; kh = t/48 (0..15) -> 4 chunks.
// h loads (broadcast) amortized over 4 rows; 24 warps hide LDS/FMA latency.
// w slot rotation by row-GROUP: slot=(chunk+(row>>2))&63 -> CF (4 phases).
// gh partials: float2 (batch0,batch1) at [kh][row], 16-way K reduction.
#define GRU_THR       768
#define GRU_NS        16
#define GRU2_W_BYTES  196608                        // 192 rows * 64 slots * 16B
#define GRU2_H_OFF    GRU2_W_BYTES                  // [2 phase][2 batch][512] f32
#define GRU2_GH_OFF   (GRU2_W_BYTES + 8192)         // [16 kh][192 row] float2
#define GRU2_SMEM     (GRU2_W_BYTES + 8192 + 24576) // 229376

__global__ __launch_bounds__(GRU_THR) __cluster_dims__(8, 1, 1)
void gru2(const float* __restrict__ gi, const float* __restrict__ Whh,
          const float* __restrict__ bhh, const float* __restrict__ h0,
          __nv_bfloat16* __restrict__ outBf, float* __restrict__ outF)
{
    extern __shared__ char sm[];
    __nv_bfloat16* w_s = (__nv_bfloat16*)sm;
    float*  h_s  = (float*)(sm + GRU2_H_OFF);
    float2* gh2  = (float2*)(sm + GRU2_GH_OFF);

    const int t = threadIdx.x;
    uint32_t rank;
    asm("mov.u32 %0, %%cluster_ctarank;" : "=r"(rank));
    const int uslc = (int)rank;
    const int b0 = (blockIdx.x >> 3) * 2;

    // weight fill: fp32 global -> bf16 smem, slot rotated by row-group
    for (int idx = t; idx < 192 * 64; idx += GRU_THR) {
        int row = idx >> 6, chunk = idx & 63;
        int G = (row >> 6) * HID + uslc * 64 + (row & 63);
        const float4* src = (const float4*)(Whh + (size_t)G * HID + chunk * 8);
        float4 v0 = src[0], v1 = src[1];
        int slot = (chunk + (row >> 2)) & 63;
        __nv_bfloat162* dst = (__nv_bfloat162*)(w_s + row * 512 + slot * 8);
        dst[0] = __floats2bfloat162_rn(v0.x, v0.y);
        dst[1] = __floats2bfloat162_rn(v0.z, v0.w);
        dst[2] = __floats2bfloat162_rn(v1.x, v1.y);
        dst[3] = __floats2bfloat162_rn(v1.z, v1.w);
    }
    for (int i = t; i < 2 * HID; i += GRU_THR) {
        int bb = i >> 9, k = i & 511;
        h_s[bb * 512 + k] = h0[(size_t)(b0 + bb) * HID + k];
    }
    const int g  = t % 48;          // row group: rows 4g..4g+3
    const int kh = t / 48;          // K-slice: chunks kh*4..kh*4+3
    const int r0w = 4 * g;
    float b_r = 0.f, b_z = 0.f, b_n = 0.f;
    int ul = 0, bb = 0, u = 0;
    if (t < 128) {
        ul = t >> 1; bb = t & 1; u = uslc * 64 + ul;
        b_r = bhh[u]; b_z = bhh[HID + u]; b_n = bhh[2 * HID + u];
    }
    __syncthreads();

    const uint4* wr0 = (const uint4*)(w_s + (r0w + 0) * 512);
    const uint4* wr1 = (const uint4*)(w_s + (r0w + 1) * 512);
    const uint4* wr2 = (const uint4*)(w_s + (r0w + 2) * 512);
    const uint4* wr3 = (const uint4*)(w_s + (r0w + 3) * 512);
    const int kh4 = kh * 4;

    for (int s = 0; s < SEQ; s++) {
        const int p = s & 1;
        float pir = 0.f, piz = 0.f, pin = 0.f;
        if (t < 128) {
            const float* gir = gi + (size_t)(s * BATCH + b0 + bb) * H3 + u;
            pir = gir[0]; piz = gir[HID]; pin = gir[2 * HID];
        }
        const float* hp = h_s + p * 1024;
        unsigned long long acc[4][2];
#pragma unroll
        for (int i = 0; i < 4; i++) { acc[i][0] = 0; acc[i][1] = 0; }
#pragma unroll
        for (int c = 0; c < 4; c++) {
            int ca = kh4 + c;
            int sl = (ca + g) & 63;
            uint4 wv0 = wr0[sl], wv1 = wr1[sl], wv2 = wr2[sl], wv3 = wr3[sl];
            int k0 = ca * 8;
            double2 xa = *(const double2*)(hp + k0);
            double2 xb = *(const double2*)(hp + k0 + 4);
            double2 ya = *(const double2*)(hp + 512 + k0);
            double2 yb = *(const double2*)(hp + 512 + k0 + 4);
            unsigned long long ha0 = __double_as_longlong(xa.x);
            unsigned long long ha1 = __double_as_longlong(xa.y);
            unsigned long long ha2 = __double_as_longlong(xb.x);
            unsigned long long ha3 = __double_as_longlong(xb.y);
            unsigned long long hb0 = __double_as_longlong(ya.x);
            unsigned long long hb1 = __double_as_longlong(ya.y);
            unsigned long long hb2 = __double_as_longlong(yb.x);
            unsigned long long hb3 = __double_as_longlong(yb.y);
#pragma unroll
            for (int i = 0; i < 4; i++) {
                uint4 wv = (i == 0) ? wv0 : (i == 1) ? wv1 : (i == 2) ? wv2 : wv3;
                unsigned long long w0 = bf2f2(wv.x);
                unsigned long long w1 = bf2f2(wv.y);
                unsigned long long w2 = bf2f2(wv.z);
                unsigned long long w3 = bf2f2(wv.w);
                acc[i][0] = fma2(w0, ha0, acc[i][0]);
                acc[i][0] = fma2(w1, ha1, acc[i][0]);
                acc[i][0] = fma2(w2, ha2, acc[i][0]);
                acc[i][0] = fma2(w3, ha3, acc[i][0]);
                acc[i][1] = fma2(w0, hb0, acc[i][1]);
                acc[i][1] = fma2(w1, hb1, acc[i][1]);
                acc[i][1] = fma2(w2, hb2, acc[i][1]);
                acc[i][1] = fma2(w3, hb3, acc[i][1]);
            }
        }
#pragma unroll
        for (int i = 0; i < 4; i++)
            gh2[kh * 192 + r0w + i] = make_float2(hsum2(acc[i][0]), hsum2(acc[i][1]));
        __syncthreads();
        if (t < 128) {
            float ghr = b_r, ghz = b_z, ghn = b_n;
#pragma unroll
            for (int k2 = 0; k2 < GRU_NS; k2++) {
                float2 vr = gh2[k2 * 192 + ul];
                float2 vz = gh2[k2 * 192 + 64 + ul];
                float2 vn = gh2[k2 * 192 + 128 + ul];
                ghr += bb ? vr.y : vr.x;
                ghz += bb ? vz.y : vz.x;
                ghn += bb ? vn.y : vn.x;
            }
            float rr = sigm(pir + ghr);
            float zz = sigm(piz + ghz);
            float nn = tanhf(pin + rr * ghn);
            float h2 = (1.f - zz) * nn + zz * hp[bb * 512 + u];
            size_t orow = (size_t)(s * BATCH + b0 + bb) * HID + u;
            outBf[orow] = __float2bfloat16(h2);
            if (outF) outF[orow] = h2;
            int wofs = (p ^ 1) * 1024 + bb * 512 + u;
            h_s[wofs] = h2;
            uint32_t laddr = (uint32_t)__cvta_generic_to_shared(&h_s[wofs]);
#pragma unroll
            for (int pr = 0; pr < 8; pr++) {
                if (pr == uslc) continue;
                uint32_t raddr;
                asm volatile("mapa.shared::cluster.u32 %0, %1, %2;"
                             : "=r"(raddr) : "r"(laddr), "r"(pr));
                asm volatile("st.shared::cluster.f32 [%0], %1;"
                             :: "r"(raddr), "f"(h2) : "memory");
            }
        }
        asm volatile("barrier.cluster.arrive.aligned;" ::: "memory");
        asm volatile("barrier.cluster.wait.aligned;" ::: "memory");
    }
}

// ---------------- small kernels ----------------
#define N_WOUT4 (VOCAB * HID / 4)
#define N_WIH04 (H3 * DIN / 4)
#define N_WIH14 (H3 * HID / 4)
#define N_WOO4  (HID * HID / 4)
#define N_CVT_TOT (N_WOUT4 + N_WIH04 + N_WIH14 + N_WOO4)

__global__ void k_cvtall(const float* __restrict__ s0, __nv_bfloat16* __restrict__ d0,
                         const float* __restrict__ s1, __nv_bfloat16* __restrict__ d1,
                         const float* __restrict__ s2, __nv_bfloat16* __restrict__ d2,
                         const float* __restrict__ s3, __nv_bfloat16* __restrict__ d3) {
    int i = blockIdx.x * blockDim.x + threadIdx.x;
    const float* s; __nv_bfloat16* d; int off;
    if (i < N_WOUT4)                               { s = s0; d = d0; off = i; }
    else if (i < N_WOUT4 + N_WIH04)                { s = s1; d = d1; off = i - N_WOUT4; }
    else if (i < N_WOUT4 + N_WIH04 + N_WIH14)      { s = s2; d = d2; off = i - N_WOUT4 - N_WIH04; }
    else if (i < N_CVT_TOT)                        { s = s3; d = d3; off = i - N_WOUT4 - N_WIH04 - N_WIH14; }
    else return;
    float4 v = ((const float4*)s)[off];
    __nv_bfloat162* o = (__nv_bfloat162*)d + 2 * off;
    o[0] = __floats2bfloat162_rn(v.x, v.y);
    o[1] = __floats2bfloat162_rn(v.z, v.w);
}

__global__ void k_emb(const int* __restrict__ seq, const float* __restrict__ word_ebd) {
    int t = blockIdx.x * blockDim.x + threadIdx.x;
    if (t >= SB * (DIN / 4)) return;
    int row = t / (DIN / 4), k = t % (DIN / 4);
    float4 v = ((const float4*)(word_ebd + (size_t)seq[row] * DIN))[k];
    __nv_bfloat162* o = (__nv_bfloat162*)(g_embBf + row * DIN) + 2 * k;
    o[0] = __floats2bfloat162_rn(v.x, v.y);
    o[1] = __floats2bfloat162_rn(v.z, v.w);
}

__global__ void k_heads(const float* __restrict__ outseq,
                        const float* Wfg, const float* bfg,
                        const float* Wrg, const float* brg,
                        const float* Wfs, const float* bfs)
{
    int t = blockIdx.x * blockDim.x + threadIdx.x;
    if (t >= SB * 18) return;
    int row = t / 18, which = t % 18;
    const float* x = outseq + (size_t)row * HID;
    const float* w;
    float bias;
    if (which == 0)      { w = Wfg;                          bias = bfg[0]; }
    else if (which == 1) { w = Wrg;                          bias = brg[0]; }
    else                 { w = Wfs + (size_t)(which - 2) * HID; bias = bfs[which - 2]; }
    float s = 0.f;
#pragma unroll 4
    for (int k = 0; k < HID; k++) s += x[k] * w[k];
    s += bias;
    if (which == 0)      g_fg[row] = sigm(s);
    else if (which == 1) g_rg[row] = sigm(s);
    else                 g_fs[row * 16 + which - 2] = s;
}

__global__ void k_scoreout(const float* __restrict__ ui_var,
                           const float* __restrict__ Wso, const float* __restrict__ bso) {
    int t = blockIdx.x * blockDim.x + threadIdx.x;
    if (t >= BATCH * HID) return;
    int b = t / HID, u = t % HID;
    float s = 0.f;
#pragma unroll
    for (int k = 0; k < 32; k++) s += ui_var[b * 32 + k] * Wso[u * 32 + k];
    g_scoreout[t] = s + bso[u];
}

__global__ void k_energy(const int* __restrict__ i_features, const float* __restrict__ word_ebd,
                         const float* __restrict__ Wfa, const float* __restrict__ bfa) {
    int t = blockIdx.x * blockDim.x + threadIdx.x;
    if (t >= BATCH * FEA * 80) return;
    int j = t % 80, bf = t / 80;
    const float* x = word_ebd + (size_t)i_features[bf] * DIN;
    const float* w = Wfa + (size_t)j * DIN;
    float s = 0.f;
#pragma unroll 4
    for (int k = 0; k < DIN; k++) s += x[k] * w[k];
    g_energy[t] = s + bfa[j];
}

__global__ void k_scores(const float* __restrict__ user, const float* __restrict__ item,
                         const int* __restrict__ mask) {
    int row = blockIdx.x;          // s*32+b
    int b = row & 31;
    __shared__ float sc[FEA];
    __shared__ float red[2];
    int f = threadIdx.x;
    if (f < FEA) {
        const float* e = g_energy + (size_t)(b * FEA + f) * 80;
        float s = 0.f;
#pragma unroll
        for (int k = 0; k < 16; k++) s += g_fs[row * 16 + k] * e[k];
#pragma unroll
        for (int k = 0; k < 32; k++) s += user[b * 32 + k] * e[16 + k];
#pragma unroll
        for (int k = 0; k < 32; k++) s += item[b * 32 + k] * e[48 + k];
        if (mask[b * FEA + f] == 0) s = -1e9f;
        sc[f] = s;
    }
    __syncthreads();
    if (threadIdx.x == 0) {
        float m = -1e30f;
        for (int i = 0; i < FEA; i++) m = fmaxf(m, sc[i]);
        float sum = 0.f;
        for (int i = 0; i < FEA; i++) sum += expf(sc[i] - m);
        red[0] = m; red[1] = sum;
    }
    __syncthreads();
    if (f < FEA) g_fattn[row * FEA + f] = expf(sc[f] - red[0]) / red[1];
}

// fused: rowsum(exp) + log-mix from bf16 logits staged in smem
__global__ __launch_bounds__(1024) void k_soft(float* __restrict__ out) {
    extern __shared__ __align__(16) __nv_bfloat16 lsb[];  // VOCAB bf16 = 64000 B
    __shared__ float red[32];
    __shared__ float cb_s;
    const int row = blockIdx.x, t = threadIdx.x;
    const uint4* src = (const uint4*)(g_logitsBf + (size_t)row * VOCAB);
    float s = 0.f;
    for (int i = t; i < VOCAB / 8; i += 1024) {
        uint4 l = src[i];
        ((uint4*)lsb)[i] = l;
        float2 p0 = __bfloat1622float2(*(__nv_bfloat162*)&l.x);
        float2 p1 = __bfloat1622float2(*(__nv_bfloat162*)&l.y);
        float2 p2 = __bfloat1622float2(*(__nv_bfloat162*)&l.z);
        float2 p3 = __bfloat1622float2(*(__nv_bfloat162*)&l.w);
        s += __expf(p0.x) + __expf(p0.y) + __expf(p1.x) + __expf(p1.y)
           + __expf(p2.x) + __expf(p2.y) + __expf(p3.x) + __expf(p3.y);
    }
#pragma unroll
    for (int o = 16; o > 0; o >>= 1) s += __shfl_down_sync(~0u, s, o);
    if ((t & 31) == 0) red[t >> 5] = s;
    __syncthreads();
    if (t < 32) {
        float v = red[t];
#pragma unroll
        for (int o = 16; o > 0; o >>= 1) v += __shfl_down_sync(~0u, v, o);
        if (t == 0) {
            g_rowsum[row] = v;
            cb_s = logf(v) - logf(1.f - g_fg[row]);
        }
    }
    __syncthreads();
    const float c = cb_s;
    float4* dst = (float4*)(out + (size_t)row * VOCAB);
    for (int i = t; i < VOCAB / 8; i += 1024) {
        uint4 l = ((const uint4*)lsb)[i];
        float2 p0 = __bfloat1622float2(*(__nv_bfloat162*)&l.x);
        float2 p1 = __bfloat1622float2(*(__nv_bfloat162*)&l.y);
        float2 p2 = __bfloat1622float2(*(__nv_bfloat162*)&l.z);
        float2 p3 = __bfloat1622float2(*(__nv_bfloat162*)&l.w);
        float4 o0, o1;
        o0.x = p0.x - c; o0.y = p0.y - c; o0.z = p1.x - c; o0.w = p1.y - c;
        o1.x = p2.x - c; o1.y = p2.y - c; o1.z = p3.x - c; o1.w = p3.y - c;
        dst[2 * i]     = o0;
        dst[2 * i + 1] = o1;
    }
}

__global__ void k_fix(const int* __restrict__ i_features, float* __restrict__ out) {
    int t = blockIdx.x * blockDim.x + threadIdx.x;
    if (t >= SB * FEA) return;
    int row = t / FEA, f = t % FEA, b = row & 31;
    int v = i_features[b * FEA + f];
    float logit = __bfloat162float(g_logitsBf[(size_t)row * VOCAB + v]);
    float fg = g_fg[row];
    float p = __expf(logit) / g_rowsum[row];
    out[(size_t)row * VOCAB + v] = logf((1.f - fg) * p + fg * g_fattn[t]);
}

// ---------------- launch ----------------
extern "C" void kernel_launch(void* const* d_in, const int* in_sizes, int n_in,
                              void* d_out, int out_size)
{
    const int*   input_seq  = (const int*)d_in[0];
    const float* init_hid   = (const float*)d_in[1];
    const float* user_vct   = (const float*)d_in[2];
    const float* item_vct   = (const float*)d_in[3];
    const float* ui_var     = (const float*)d_in[4];
    const int*   i_features = (const int*)d_in[5];
    const int*   if_mask    = (const int*)d_in[6];    // bool -> int32 in harness
    const float* word_ebd = (const float*)d_in[7];
    const float* Wih0 = (const float*)d_in[8];  const float* Whh0 = (const float*)d_in[9];
    const float* bih0 = (const float*)d_in[10]; const float* bhh0 = (const float*)d_in[11];
    const float* Wih1 = (const float*)d_in[12]; const float* Whh1 = (const float*)d_in[13];
    const float* bih1 = (const float*)d_in[14]; const float* bhh1 = (const float*)d_in[15];
    const float* Wout = (const float*)d_in[16]; const float* bout = (const float*)d_in[17];
    const float* Wrg  = (const float*)d_in[18]; const float* brg  = (const float*)d_in[19];
    const float* Wso  = (const float*)d_in[20]; const float* bso  = (const float*)d_in[21];
    const float* Woo  = (const float*)d_in[22]; const float* boo  = (const float*)d_in[23];
    const float* Wfg  = (const float*)d_in[24]; const float* bfg  = (const float*)d_in[25];
    const float* Wfs  = (const float*)d_in[26]; const float* bfs  = (const float*)d_in[27];
    const float* Wfa  = (const float*)d_in[28]; const float* bfa  = (const float*)d_in[29];
    float* out = (float*)d_out;

    __nv_bfloat16 *embBf, *wih0Bf, *wih1Bf, *wooBf, *woutBf, *h0Bf, *outBf, *actBf, *logitsBf;
    float *gi, *outseq, *rgP, *soP;
    cudaGetSymbolAddress((void**)&embBf,  g_embBf);
    cudaGetSymbolAddress((void**)&wih0Bf, g_Wih0Bf);
    cudaGetSymbolAddress((void**)&wih1Bf, g_Wih1Bf);
    cudaGetSymbolAddress((void**)&wooBf,  g_WooBf);
    cudaGetSymbolAddress((void**)&woutBf, g_WoutBf);
    cudaGetSymbolAddress((void**)&h0Bf,   g_h0Bf);
    cudaGetSymbolAddress((void**)&outBf,  g_outBf);
    cudaGetSymbolAddress((void**)&actBf,  g_actBf);
    cudaGetSymbolAddress((void**)&logitsBf, g_logitsBf);
    cudaGetSymbolAddress((void**)&gi,     g_gi);
    cudaGetSymbolAddress((void**)&outseq, g_outseq);
    cudaGetSymbolAddress((void**)&rgP,    g_rg);
    cudaGetSymbolAddress((void**)&soP,    g_scoreout);

    cudaFuncSetAttribute(gemm_hmma<128>, cudaFuncAttributeMaxDynamicSharedMemorySize, 4 * (128 * 64 + 8192));
    cudaFuncSetAttribute(gemm_hmma<64>,  cudaFuncAttributeMaxDynamicSharedMemorySize, 4 * (64 * 64 + 8192));
    cudaFuncSetAttribute(gru2,   cudaFuncAttributeMaxDynamicSharedMemorySize, GRU2_SMEM);
    cudaFuncSetAttribute(k_soft, cudaFuncAttributeMaxDynamicSharedMemorySize, VOCAB * 2);

    // 0: all weight conversions in one launch
    k_cvtall<<<(N_CVT_TOT + 255) / 256, 256>>>(Wout, woutBf, Wih0, wih0Bf,
                                               Wih1, wih1Bf, Woo, wooBf);
    // 1: embedding gather
    k_emb<<<(SB * DIN / 4 + 255) / 256, 256>>>(input_seq, word_ebd);

    // 2-3: layer 0
    gemm_hmma<64><<<dim3(H3 / 128, SB / 64), 256, 4 * (64 * 64 + 8192)>>>(
        embBf, wih0Bf, bih0, gi, nullptr, nullptr, nullptr, H3, DIN);
    gru2<<<128, GRU_THR, GRU2_SMEM>>>(gi, Whh0, bhh0, init_hid, h0Bf, nullptr);

    // 4-5: layer 1
    gemm_hmma<64><<<dim3(H3 / 128, SB / 64), 256, 4 * (64 * 64 + 8192)>>>(
        h0Bf, wih1Bf, bih1, gi, nullptr, nullptr, nullptr, H3, HID);
    gru2<<<128, GRU_THR, GRU2_SMEM>>>(gi, Whh1, bhh1, init_hid + BATCH * HID, outBf, outseq);

    // heads on GRU output (pre-transform)
    k_heads<<<(SB * 18 + 255) / 256, 256>>>(outseq, Wfg, bfg, Wrg, brg, Wfs, bfs);
    k_scoreout<<<(BATCH * HID + 255) / 256, 256>>>(ui_var, Wso, bso);
    k_energy<<<(BATCH * FEA * 80 + 255) / 256, 256>>>(i_features, word_ebd, Wfa, bfa);
    k_scores<<<SB, 64>>>(user_vct, item_vct, if_mask);

    // output transform fused: actBf = tanh(out @ Woo^T + boo + rg*score_out)
    gemm_hmma<64><<<dim3(HID / 128, SB / 64), 256, 4 * (64 * 64 + 8192)>>>(
        outBf, wooBf, boo, nullptr, actBf, rgP, soP, HID, HID);

    // big vocab GEMM (bf16 logits, 512 threads, no spills) + fused softmax
    gemm_hmma<128><<<dim3(VOCAB / 128, SB / 128), 512, 4 * (128 * 64 + 8192)>>>(
        actBf, woutBf, bout, nullptr, logitsBf, nullptr, nullptr, VOCAB, HID);
    k_soft<<<SB, 1024, VOCAB * 2>>>(out);
    k_fix<<<(SB * FEA + 63) / 64, 64>>>(i_features, out);
}

// round 16
// speedup vs baseline: 1.0130x; 1.0130x over previous
#include <cuda_runtime.h>
#include <cuda_bf16.h>
#include <cstdint>

// ---------------- problem dims ----------------
#define SEQ    32
#define BATCH  32
#define SB     1024          // SEQ*BATCH
#define HID    512
#define H3     1536
#define DIN    512
#define VOCAB  32000
#define FEA    50

// ---------------- scratch (static device, no allocs) ----------------
__device__ __align__(16) __nv_bfloat16 g_embBf [SB * DIN];
__device__ __align__(16) __nv_bfloat16 g_Wih0Bf[H3 * DIN];
__device__ __align__(16) __nv_bfloat16 g_Wih1Bf[H3 * HID];
__device__ __align__(16) __nv_bfloat16 g_WooBf [HID * HID];
__device__ __align__(16) __nv_bfloat16 g_WoutBf[(size_t)VOCAB * HID];
__device__ __align__(16) float g_gi     [SB * H3];
__device__ __align__(16) __nv_bfloat16 g_h0Bf [SB * HID];
__device__ __align__(16) float g_outseq [SB * HID];
__device__ __align__(16) __nv_bfloat16 g_outBf[SB * HID];
__device__ __align__(16) __nv_bfloat16 g_actBf[SB * HID];
__device__ __align__(16) __nv_bfloat16 g_logitsBf[(size_t)SB * VOCAB];  // 65 MB
__device__ float g_fg[SB], g_rg[SB];
__device__ float g_fs[SB * 16];
__device__ float g_scoreout[BATCH * HID];
__device__ float g_energy[BATCH * FEA * 80];
__device__ float g_fattn[SB * FEA];

__device__ __forceinline__ float sigm(float x) { return 1.f / (1.f + expf(-x)); }

// packed dual-fp32 FMA (Blackwell f32x2 pipe; PTX-only form)
__device__ __forceinline__ unsigned long long fma2(unsigned long long a,
                                                   unsigned long long b,
                                                   unsigned long long c) {
    unsigned long long d;
    asm("fma.rn.f32x2 %0,%1,%2,%3;" : "=l"(d) : "l"(a), "l"(b), "l"(c));
    return d;
}
__device__ __forceinline__ float hsum2(unsigned long long v) {
    uint32_t lo, hi;
    asm("mov.b64 {%0,%1},%2;" : "=r"(lo), "=r"(hi) : "l"(v));
    return __uint_as_float(lo) + __uint_as_float(hi);
}
// bf16x2 (packed in u32) -> f32x2 (packed in u64)
__device__ __forceinline__ unsigned long long bf2f2(uint32_t v) {
    uint32_t lo = v << 16;
    uint32_t hi = v & 0xFFFF0000u;
    unsigned long long d;
    asm("mov.b64 %0,{%1,%2};" : "=l"(d) : "r"(lo), "r"(hi));
    return d;
}

// ---------------- HMMA bf16 GEMM: C[M,N] = A[M,K] @ B[N,K]^T + bias[N] ----
// BM=128: 8 warps 2m x 4n (128x128 tile). BM=64: 8 warps 1m x 8n (64x128).
// 4-stage cp.async pipeline, 1 __syncthreads per K-chunk, 2 CTAs/SM.
// smem rows of 32 bf16 (64B), chunk-XOR swizzle (conflict-free ldmatrix+fill).
// Cbf!=null -> bf16 out; RG!=null -> tanh(acc+bias+rg*so) bf16 out.
#define BK 32

__device__ __forceinline__ uint32_t sw_off(int row, int chunk) {
    return (uint32_t)(row * 64 + ((chunk ^ ((row >> 1) & 3)) << 4));
}

template<int BM>
__global__ __launch_bounds__(256, 2) void gemm_hmma(
    const __nv_bfloat16* __restrict__ A, const __nv_bfloat16* __restrict__ B,
    const float* __restrict__ bias, float* __restrict__ C,
    __nv_bfloat16* __restrict__ Cbf,
    const float* __restrict__ RG, const float* __restrict__ SO,
    int N, int K)
{
    constexpr int ASZ = BM * 64;         // A stage bytes
    constexpr int BSZ = 128 * 64;        // B stage bytes
    constexpr int SST = ASZ + BSZ;       // stage stride
    constexpr int NI  = (BM == 128) ? 4 : 2;
    extern __shared__ __align__(128) char gsm[];
    const int bm = blockIdx.y * BM, bn = blockIdx.x * 128;
    const int tid = threadIdx.x;
    const int warp = tid >> 5, lane = tid & 31;
    const int wm = (BM == 128) ? (warp & 1) * 64 : 0;
    const int wn = (BM == 128) ? (warp >> 1) * 32 : warp * 16;

    const uint32_t sBase = (uint32_t)__cvta_generic_to_shared(gsm);
    const int nk = K / BK;

    float acc[4][NI][4];
#pragma unroll
    for (int i = 0; i < 4; i++)
#pragma unroll
        for (int j = 0; j < NI; j++)
#pragma unroll
            for (int k = 0; k < 4; k++) acc[i][j][k] = 0.f;

    const int fr = tid >> 2, fc = tid & 3;
    auto issue = [&](int st, int kc) {
        if (kc < nk) {
            const __nv_bfloat16* Ag = A + (size_t)(bm + fr) * K + kc * BK + fc * 8;
            const __nv_bfloat16* Bg = B + (size_t)(bn + fr) * K + kc * BK + fc * 8;
            uint32_t aB = sBase + (uint32_t)(st * SST);
            uint32_t bB = aB + ASZ;
            asm volatile("cp.async.cg.shared.global [%0],[%1],16;"
                         :: "r"(aB + sw_off(fr, fc)), "l"(Ag));
            if (BM == 128)
                asm volatile("cp.async.cg.shared.global [%0],[%1],16;"
                             :: "r"(aB + sw_off(fr + 64, fc)), "l"(Ag + (size_t)64 * K));
            asm volatile("cp.async.cg.shared.global [%0],[%1],16;"
                         :: "r"(bB + sw_off(fr, fc)), "l"(Bg));
            asm volatile("cp.async.cg.shared.global [%0],[%1],16;"
                         :: "r"(bB + sw_off(fr + 64, fc)), "l"(Bg + (size_t)64 * K));
        }
        asm volatile("cp.async.commit_group;");
    };

    issue(0, 0); issue(1, 1); issue(2, 2);

    for (int kt = 0; kt < nk; kt++) {
        const int cur = kt & 3;
        asm volatile("cp.async.wait_group 2;");
        __syncthreads();
        issue((kt + 3) & 3, kt + 3);
        const uint32_t aC = sBase + (uint32_t)(cur * SST);
        const uint32_t bC = aC + ASZ;
#pragma unroll
        for (int kk = 0; kk < 2; kk++) {
            const int kb = kk * 2;
            uint32_t a[4][4], b[NI][2];
#pragma unroll
            for (int mi = 0; mi < 4; mi++) {
                int row = wm + mi * 16 + (lane & 15);
                uint32_t addr = aC + sw_off(row, kb + (lane >> 4));
                asm volatile("ldmatrix.sync.aligned.m8n8.x4.shared.b16 {%0,%1,%2,%3}, [%4];"
                             : "=r"(a[mi][0]), "=r"(a[mi][1]), "=r"(a[mi][2]), "=r"(a[mi][3])
                             : "r"(addr));
            }
#pragma unroll
            for (int ni = 0; ni < NI; ni++) {
                int row = wn + ni * 8 + (lane & 7);
                uint32_t addr = bC + sw_off(row, kb + ((lane >> 3) & 1));
                asm volatile("ldmatrix.sync.aligned.m8n8.x2.shared.b16 {%0,%1}, [%2];"
                             : "=r"(b[ni][0]), "=r"(b[ni][1]) : "r"(addr));
            }
#pragma unroll
            for (int mi = 0; mi < 4; mi++)
#pragma unroll
                for (int ni = 0; ni < NI; ni++) {
                    asm volatile(
                        "mma.sync.aligned.m16n8k16.row.col.f32.bf16.bf16.f32 "
                        "{%0,%1,%2,%3},{%4,%5,%6,%7},{%8,%9},{%0,%1,%2,%3};\n"
                        : "+f"(acc[mi][ni][0]), "+f"(acc[mi][ni][1]),
                          "+f"(acc[mi][ni][2]), "+f"(acc[mi][ni][3])
                        : "r"(a[mi][0]), "r"(a[mi][1]), "r"(a[mi][2]), "r"(a[mi][3]),
                          "r"(b[ni][0]), "r"(b[ni][1]));
                }
        }
    }

    const int g = lane >> 2, tg = lane & 3;
#pragma unroll
    for (int mi = 0; mi < 4; mi++)
#pragma unroll
        for (int ni = 0; ni < NI; ni++) {
            int row = bm + wm + mi * 16 + g;
            int col = bn + wn + ni * 8 + tg * 2;
            float b0 = bias[col], b1 = bias[col + 1];
            float v0 = acc[mi][ni][0] + b0, v1 = acc[mi][ni][1] + b1;
            float v2 = acc[mi][ni][2] + b0, v3 = acc[mi][ni][3] + b1;
            if (RG) {
                int ba = row & 31, bb = (row + 8) & 31;
                float r0 = RG[row], r1 = RG[row + 8];
                v0 = tanhf(v0 + r0 * SO[ba * HID + col]);
                v1 = tanhf(v1 + r0 * SO[ba * HID + col + 1]);
                v2 = tanhf(v2 + r1 * SO[bb * HID + col]);
                v3 = tanhf(v3 + r1 * SO[bb * HID + col + 1]);
            }
            if (Cbf) {
                *(__nv_bfloat162*)&Cbf[(size_t)row * N + col] = __floats2bfloat162_rn(v0, v1);
                *(__nv_bfloat162*)&Cbf[(size_t)(row + 8) * N + col] = __floats2bfloat162_rn(v2, v3);
            } else {
                C[(size_t)row * N + col]           = v0;
                C[(size_t)row * N + col + 1]       = v1;
                C[(size_t)(row + 8) * N + col]     = v2;
                C[(size_t)(row + 8) * N + col + 1] = v3;
            }
        }
}

// ---------------- GRU v5b: cluster-of-8, smem weights, 4 rows/thread -------
// 128 CTAs x 384 threads, clusters of 8. Cluster = one batch-pair.
// CTA rank = u-slice (64 units x 3 gates = 192 rows, 196KB bf16 in smem).
// Thread (g, kh): g = t%48 -> rows 4g..4g+3; kh = t/48 -> chunks kh*8..kh*8+7.
// h loads (broadcast) amortized over 4 rows.
// w slot rotation by row-GROUP: slot=(chunk+(row>>2))&63 -> lane-linear, CF.
// gh partials: float2 (batch0,batch1) at [kh][row], 8-way K reduction.
// Remote DSMEM addresses (7 peers x 2 phases) hoisted out of the step loop.
#define GRU_THR       384
#define GRU2_W_BYTES  196608                        // 192 rows * 64 slots * 16B
#define GRU2_H_OFF    GRU2_W_BYTES                  // [2 phase][2 batch][512] f32
#define GRU2_GH_OFF   (GRU2_W_BYTES + 8192)         // [8 kh][192 row] float2
#define GRU2_SMEM     (GRU2_W_BYTES + 8192 + 12288) // 217088

__global__ __launch_bounds__(GRU_THR) __cluster_dims__(8, 1, 1)
void gru2(const float* __restrict__ gi, const float* __restrict__ Whh,
          const float* __restrict__ bhh, const float* __restrict__ h0,
          __nv_bfloat16* __restrict__ outBf, float* __restrict__ outF)
{
    extern __shared__ char sm[];
    __nv_bfloat16* w_s = (__nv_bfloat16*)sm;
    float*  h_s  = (float*)(sm + GRU2_H_OFF);
    float2* gh2  = (float2*)(sm + GRU2_GH_OFF);

    const int t = threadIdx.x;
    uint32_t rank;
    asm("mov.u32 %0, %%cluster_ctarank;" : "=r"(rank));
    const int uslc = (int)rank;
    const int b0 = (blockIdx.x >> 3) * 2;

    // weight fill: fp32 global -> bf16 smem, slot rotated by row-group
    for (int idx = t; idx < 192 * 64; idx += GRU_THR) {
        int row = idx >> 6, chunk = idx & 63;
        int G = (row >> 6) * HID + uslc * 64 + (row & 63);
        const float4* src = (const float4*)(Whh + (size_t)G * HID + chunk * 8);
        float4 v0 = src[0], v1 = src[1];
        int slot = (chunk + (row >> 2)) & 63;
        __nv_bfloat162* dst = (__nv_bfloat162*)(w_s + row * 512 + slot * 8);
        dst[0] = __floats2bfloat162_rn(v0.x, v0.y);
        dst[1] = __floats2bfloat162_rn(v0.z, v0.w);
        dst[2] = __floats2bfloat162_rn(v1.x, v1.y);
        dst[3] = __floats2bfloat162_rn(v1.z, v1.w);
    }
    for (int i = t; i < 2 * HID; i += GRU_THR) {
        int bb = i >> 9, k = i & 511;
        h_s[bb * 512 + k] = h0[(size_t)(b0 + bb) * HID + k];
    }
    const int g  = t % 48;          // row group: rows 4g..4g+3
    const int kh = t / 48;          // K-slice: chunks kh*8..kh*8+7
    const int r0w = 4 * g;
    float b_r = 0.f, b_z = 0.f, b_n = 0.f;
    int ul = 0, bb = 0, u = 0;
    uint32_t raddr[2][7];
    int wofs2[2];
    if (t < 128) {
        ul = t >> 1; bb = t & 1; u = uslc * 64 + ul;
        b_r = bhh[u]; b_z = bhh[HID + u]; b_n = bhh[2 * HID + u];
#pragma unroll
        for (int ph = 0; ph < 2; ph++) {
            wofs2[ph] = ph * 1024 + bb * 512 + u;
            uint32_t laddr = (uint32_t)__cvta_generic_to_shared(&h_s[wofs2[ph]]);
            int j = 0;
#pragma unroll
            for (int pr = 0; pr < 8; pr++) {
                if (pr == uslc) continue;
                uint32_t ra;
                asm volatile("mapa.shared::cluster.u32 %0, %1, %2;"
                             : "=r"(ra) : "r"(laddr), "r"(pr));
                raddr[ph][j++] = ra;
            }
        }
    }
    __syncthreads();

    const uint4* wr0 = (const uint4*)(w_s + (r0w + 0) * 512);
    const uint4* wr1 = (const uint4*)(w_s + (r0w + 1) * 512);
    const uint4* wr2 = (const uint4*)(w_s + (r0w + 2) * 512);
    const uint4* wr3 = (const uint4*)(w_s + (r0w + 3) * 512);
    const int kh8 = kh * 8;

    for (int s = 0; s < SEQ; s++) {
        const int p = s & 1;
        float pir = 0.f, piz = 0.f, pin = 0.f;
        if (t < 128) {
            const float* gir = gi + (size_t)(s * BATCH + b0 + bb) * H3 + u;
            pir = gir[0]; piz = gir[HID]; pin = gir[2 * HID];
        }
        const float* hp = h_s + p * 1024;
        unsigned long long acc[4][2];
#pragma unroll
        for (int i = 0; i < 4; i++) { acc[i][0] = 0; acc[i][1] = 0; }
#pragma unroll
        for (int c = 0; c < 8; c++) {
            int ca = kh8 + c;
            int sl = (ca + g) & 63;
            uint4 wv0 = wr0[sl], wv1 = wr1[sl], wv2 = wr2[sl], wv3 = wr3[sl];
            int k0 = ca * 8;
            double2 xa = *(const double2*)(hp + k0);
            double2 xb = *(const double2*)(hp + k0 + 4);
            double2 ya = *(const double2*)(hp + 512 + k0);
            double2 yb = *(const double2*)(hp + 512 + k0 + 4);
            unsigned long long ha0 = __double_as_longlong(xa.x);
            unsigned long long ha1 = __double_as_longlong(xa.y);
            unsigned long long ha2 = __double_as_longlong(xb.x);
            unsigned long long ha3 = __double_as_longlong(xb.y);
            unsigned long long hb0 = __double_as_longlong(ya.x);
            unsigned long long hb1 = __double_as_longlong(ya.y);
            unsigned long long hb2 = __double_as_longlong(yb.x);
            unsigned long long hb3 = __double_as_longlong(yb.y);
#pragma unroll
            for (int i = 0; i < 4; i++) {
                uint4 wv = (i == 0) ? wv0 : (i == 1) ? wv1 : (i == 2) ? wv2 : wv3;
                unsigned long long w0 = bf2f2(wv.x);
                unsigned long long w1 = bf2f2(wv.y);
                unsigned long long w2 = bf2f2(wv.z);
                unsigned long long w3 = bf2f2(wv.w);
                acc[i][0] = fma2(w0, ha0, acc[i][0]);
                acc[i][0] = fma2(w1, ha1, acc[i][0]);
                acc[i][0] = fma2(w2, ha2, acc[i][0]);
                acc[i][0] = fma2(w3, ha3, acc[i][0]);
                acc[i][1] = fma2(w0, hb0, acc[i][1]);
                acc[i][1] = fma2(w1, hb1, acc[i][1]);
                acc[i][1] = fma2(w2, hb2, acc[i][1]);
                acc[i][1] = fma2(w3, hb3, acc[i][1]);
            }
        }
#pragma unroll
        for (int i = 0; i < 4; i++)
            gh2[kh * 192 + r0w + i] = make_float2(hsum2(acc[i][0]), hsum2(acc[i][1]));
        __syncthreads();
        if (t < 128) {
            float ghr = b_r, ghz = b_z, ghn = b_n;
#pragma unroll
            for (int k2 = 0; k2 < 8; k2++) {
                float2 vr = gh2[k2 * 192 + ul];
                float2 vz = gh2[k2 * 192 + 64 + ul];
                float2 vn = gh2[k2 * 192 + 128 + ul];
                ghr += bb ? vr.y : vr.x;
                ghz += bb ? vz.y : vz.x;
                ghn += bb ? vn.y : vn.x;
            }
            float rr = sigm(pir + ghr);
            float zz = sigm(piz + ghz);
            float nn = tanhf(pin + rr * ghn);
            float h2 = (1.f - zz) * nn + zz * hp[bb * 512 + u];
            size_t orow = (size_t)(s * BATCH + b0 + bb) * HID + u;
            outBf[orow] = __float2bfloat16(h2);
            if (outF) outF[orow] = h2;
            const int ph = p ^ 1;
            h_s[wofs2[ph]] = h2;
#pragma unroll
            for (int j = 0; j < 7; j++)
                asm volatile("st.shared::cluster.f32 [%0], %1;"
                             :: "r"(raddr[ph][j]), "f"(h2) : "memory");
        }
        asm volatile("barrier.cluster.arrive.aligned;" ::: "memory");
        asm volatile("barrier.cluster.wait.aligned;" ::: "memory");
    }
}

// ---------------- small kernels ----------------
#define N_WOUT4 (VOCAB * HID / 4)
#define N_WIH04 (H3 * DIN / 4)
#define N_WIH14 (H3 * HID / 4)
#define N_WOO4  (HID * HID / 4)
#define N_CVT_TOT (N_WOUT4 + N_WIH04 + N_WIH14 + N_WOO4)

__global__ void k_cvtall(const float* __restrict__ s0, __nv_bfloat16* __restrict__ d0,
                         const float* __restrict__ s1, __nv_bfloat16* __restrict__ d1,
                         const float* __restrict__ s2, __nv_bfloat16* __restrict__ d2,
                         const float* __restrict__ s3, __nv_bfloat16* __restrict__ d3) {
    int i = blockIdx.x * blockDim.x + threadIdx.x;
    const float* s; __nv_bfloat16* d; int off;
    if (i < N_WOUT4)                               { s = s0; d = d0; off = i; }
    else if (i < N_WOUT4 + N_WIH04)                { s = s1; d = d1; off = i - N_WOUT4; }
    else if (i < N_WOUT4 + N_WIH04 + N_WIH14)      { s = s2; d = d2; off = i - N_WOUT4 - N_WIH04; }
    else if (i < N_CVT_TOT)                        { s = s3; d = d3; off = i - N_WOUT4 - N_WIH04 - N_WIH14; }
    else return;
    float4 v = ((const float4*)s)[off];
    __nv_bfloat162* o = (__nv_bfloat162*)d + 2 * off;
    o[0] = __floats2bfloat162_rn(v.x, v.y);
    o[1] = __floats2bfloat162_rn(v.z, v.w);
}

__global__ void k_emb(const int* __restrict__ seq, const float* __restrict__ word_ebd) {
    int t = blockIdx.x * blockDim.x + threadIdx.x;
    if (t >= SB * (DIN / 4)) return;
    int row = t / (DIN / 4), k = t % (DIN / 4);
    float4 v = ((const float4*)(word_ebd + (size_t)seq[row] * DIN))[k];
    __nv_bfloat162* o = (__nv_bfloat162*)(g_embBf + row * DIN) + 2 * k;
    o[0] = __floats2bfloat162_rn(v.x, v.y);
    o[1] = __floats2bfloat162_rn(v.z, v.w);
}

// merged heads (fg/rg/fs) + scoreout + energy: all independent dot products
#define HSO_N0 (SB * 18)
#define HSO_N1 (BATCH * HID)
#define HSO_N2 (BATCH * FEA * 80)
#define HSO_TOT (HSO_N0 + HSO_N1 + HSO_N2)

__global__ void k_hso(const float* __restrict__ outseq,
                      const float* Wfg, const float* bfg,
                      const float* Wrg, const float* brg,
                      const float* Wfs, const float* bfs,
                      const float* __restrict__ ui_var,
                      const float* __restrict__ Wso, const float* __restrict__ bso,
                      const int* __restrict__ i_features,
                      const float* __restrict__ word_ebd,
                      const float* __restrict__ Wfa, const float* __restrict__ bfa)
{
    int t = blockIdx.x * blockDim.x + threadIdx.x;
    if (t < HSO_N0) {
        int row = t / 18, which = t % 18;
        const float* x = outseq + (size_t)row * HID;
        const float* w;
        float bias;
        if (which == 0)      { w = Wfg;                          bias = bfg[0]; }
        else if (which == 1) { w = Wrg;                          bias = brg[0]; }
        else                 { w = Wfs + (size_t)(which - 2) * HID; bias = bfs[which - 2]; }
        float s = 0.f;
#pragma unroll 4
        for (int k = 0; k < HID; k++) s += x[k] * w[k];
        s += bias;
        if (which == 0)      g_fg[row] = sigm(s);
        else if (which == 1) g_rg[row] = sigm(s);
        else                 g_fs[row * 16 + which - 2] = s;
        return;
    }
    t -= HSO_N0;
    if (t < HSO_N1) {
        int b = t / HID, u = t % HID;
        float s = 0.f;
#pragma unroll
        for (int k = 0; k < 32; k++) s += ui_var[b * 32 + k] * Wso[u * 32 + k];
        g_scoreout[t] = s + bso[u];
        return;
    }
    t -= HSO_N1;
    if (t < HSO_N2) {
        int j = t % 80, bf = t / 80;
        const float* x = word_ebd + (size_t)i_features[bf] * DIN;
        const float* w = Wfa + (size_t)j * DIN;
        float s = 0.f;
#pragma unroll 4
        for (int k = 0; k < DIN; k++) s += x[k] * w[k];
        g_energy[t] = s + bfa[j];
    }
}

__global__ void k_scores(const float* __restrict__ user, const float* __restrict__ item,
                         const int* __restrict__ mask) {
    int row = blockIdx.x;          // s*32+b
    int b = row & 31;
    __shared__ float sc[FEA];
    __shared__ float red[2];
    int f = threadIdx.x;
    if (f < FEA) {
        const float* e = g_energy + (size_t)(b * FEA + f) * 80;
        float s = 0.f;
#pragma unroll
        for (int k = 0; k < 16; k++) s += g_fs[row * 16 + k] * e[k];
#pragma unroll
        for (int k = 0; k < 32; k++) s += user[b * 32 + k] * e[16 + k];
#pragma unroll
        for (int k = 0; k < 32; k++) s += item[b * 32 + k] * e[48 + k];
        if (mask[b * FEA + f] == 0) s = -1e9f;
        sc[f] = s;
    }
    __syncthreads();
    if (threadIdx.x == 0) {
        float m = -1e30f;
        for (int i = 0; i < FEA; i++) m = fmaxf(m, sc[i]);
        float sum = 0.f;
        for (int i = 0; i < FEA; i++) sum += expf(sc[i] - m);
        red[0] = m; red[1] = sum;
    }
    __syncthreads();
    if (f < FEA) g_fattn[row * FEA + f] = expf(sc[f] - red[0]) / red[1];
}

// fused: rowsum(exp) + log-mix + scattered feature fix, from bf16 logits in smem
__global__ __launch_bounds__(1024) void k_soft(const int* __restrict__ i_features,
                                               float* __restrict__ out) {
    extern __shared__ __align__(16) __nv_bfloat16 lsb[];  // VOCAB bf16 = 64000 B
    __shared__ float red[32];
    __shared__ float cb_s, rs_s;
    const int row = blockIdx.x, t = threadIdx.x;
    const uint4* src = (const uint4*)(g_logitsBf + (size_t)row * VOCAB);
    float s = 0.f;
    for (int i = t; i < VOCAB / 8; i += 1024) {
        uint4 l = src[i];
        ((uint4*)lsb)[i] = l;
        float2 p0 = __bfloat1622float2(*(__nv_bfloat162*)&l.x);
        float2 p1 = __bfloat1622float2(*(__nv_bfloat162*)&l.y);
        float2 p2 = __bfloat1622float2(*(__nv_bfloat162*)&l.z);
        float2 p3 = __bfloat1622float2(*(__nv_bfloat162*)&l.w);
        s += __expf(p0.x) + __expf(p0.y) + __expf(p1.x) + __expf(p1.y)
           + __expf(p2.x) + __expf(p2.y) + __expf(p3.x) + __expf(p3.y);
    }
#pragma unroll
    for (int o = 16; o > 0; o >>= 1) s += __shfl_down_sync(~0u, s, o);
    if ((t & 31) == 0) red[t >> 5] = s;
    __syncthreads();
    if (t < 32) {
        float v = red[t];
#pragma unroll
        for (int o = 16; o > 0; o >>= 1) v += __shfl_down_sync(~0u, v, o);
        if (t == 0) {
            rs_s = v;
            cb_s = logf(v) - logf(1.f - g_fg[row]);
        }
    }
    __syncthreads();
    const float c = cb_s;
    float4* dst = (float4*)(out + (size_t)row * VOCAB);
    for (int i = t; i < VOCAB / 8; i += 1024) {
        uint4 l = ((const uint4*)lsb)[i];
        float2 p0 = __bfloat1622float2(*(__nv_bfloat162*)&l.x);
        float2 p1 = __bfloat1622float2(*(__nv_bfloat162*)&l.y);
        float2 p2 = __bfloat1622float2(*(__nv_bfloat162*)&l.z);
        float2 p3 = __bfloat1622float2(*(__nv_bfloat162*)&l.w);
        float4 o0, o1;
        o0.x = p0.x - c; o0.y = p0.y - c; o0.z = p1.x - c; o0.w = p1.y - c;
        o1.x = p2.x - c; o1.y = p2.y - c; o1.z = p3.x - c; o1.w = p3.y - c;
        dst[2 * i]     = o0;
        dst[2 * i + 1] = o1;
    }
    __syncthreads();
    if (t < FEA) {
        int b = row & 31;
        int v = i_features[b * FEA + t];
        float logit = __bfloat162float(lsb[v]);
        float fg = g_fg[row];
        float p = __expf(logit) / rs_s;
        out[(size_t)row * VOCAB + v] = logf((1.f - fg) * p + fg * g_fattn[row * FEA + t]);
    }
}

// ---------------- launch ----------------
extern "C" void kernel_launch(void* const* d_in, const int* in_sizes, int n_in,
                              void* d_out, int out_size)
{
    const int*   input_seq  = (const int*)d_in[0];
    const float* init_hid   = (const float*)d_in[1];
    const float* user_vct   = (const float*)d_in[2];
    const float* item_vct   = (const float*)d_in[3];
    const float* ui_var     = (const float*)d_in[4];
    const int*   i_features = (const int*)d_in[5];
    const int*   if_mask    = (const int*)d_in[6];    // bool -> int32 in harness
    const float* word_ebd = (const float*)d_in[7];
    const float* Wih0 = (const float*)d_in[8];  const float* Whh0 = (const float*)d_in[9];
    const float* bih0 = (const float*)d_in[10]; const float* bhh0 = (const float*)d_in[11];
    const float* Wih1 = (const float*)d_in[12]; const float* Whh1 = (const float*)d_in[13];
    const float* bih1 = (const float*)d_in[14]; const float* bhh1 = (const float*)d_in[15];
    const float* Wout = (const float*)d_in[16]; const float* bout = (const float*)d_in[17];
    const float* Wrg  = (const float*)d_in[18]; const float* brg  = (const float*)d_in[19];
    const float* Wso  = (const float*)d_in[20]; const float* bso  = (const float*)d_in[21];
    const float* Woo  = (const float*)d_in[22]; const float* boo  = (const float*)d_in[23];
    const float* Wfg  = (const float*)d_in[24]; const float* bfg  = (const float*)d_in[25];
    const float* Wfs  = (const float*)d_in[26]; const float* bfs  = (const float*)d_in[27];
    const float* Wfa  = (const float*)d_in[28]; const float* bfa  = (const float*)d_in[29];
    float* out = (float*)d_out;

    __nv_bfloat16 *embBf, *wih0Bf, *wih1Bf, *wooBf, *woutBf, *h0Bf, *outBf, *actBf, *logitsBf;
    float *gi, *outseq, *rgP, *soP;
    cudaGetSymbolAddress((void**)&embBf,  g_embBf);
    cudaGetSymbolAddress((void**)&wih0Bf, g_Wih0Bf);
    cudaGetSymbolAddress((void**)&wih1Bf, g_Wih1Bf);
    cudaGetSymbolAddress((void**)&wooBf,  g_WooBf);
    cudaGetSymbolAddress((void**)&woutBf, g_WoutBf);
    cudaGetSymbolAddress((void**)&h0Bf,   g_h0Bf);
    cudaGetSymbolAddress((void**)&outBf,  g_outBf);
    cudaGetSymbolAddress((void**)&actBf,  g_actBf);
    cudaGetSymbolAddress((void**)&logitsBf, g_logitsBf);
    cudaGetSymbolAddress((void**)&gi,     g_gi);
    cudaGetSymbolAddress((void**)&outseq, g_outseq);
    cudaGetSymbolAddress((void**)&rgP,    g_rg);
    cudaGetSymbolAddress((void**)&soP,    g_scoreout);

    cudaFuncSetAttribute(gemm_hmma<128>, cudaFuncAttributeMaxDynamicSharedMemorySize, 4 * (128 * 64 + 8192));
    cudaFuncSetAttribute(gemm_hmma<64>,  cudaFuncAttributeMaxDynamicSharedMemorySize, 4 * (64 * 64 + 8192));
    cudaFuncSetAttribute(gru2,   cudaFuncAttributeMaxDynamicSharedMemorySize, GRU2_SMEM);
    cudaFuncSetAttribute(k_soft, cudaFuncAttributeMaxDynamicSharedMemorySize, VOCAB * 2);

    // 0: all weight conversions in one launch
    k_cvtall<<<(N_CVT_TOT + 255) / 256, 256>>>(Wout, woutBf, Wih0, wih0Bf,
                                               Wih1, wih1Bf, Woo, wooBf);
    // 1: embedding gather
    k_emb<<<(SB * DIN / 4 + 255) / 256, 256>>>(input_seq, word_ebd);

    // 2-3: layer 0
    gemm_hmma<64><<<dim3(H3 / 128, SB / 64), 256, 4 * (64 * 64 + 8192)>>>(
        embBf, wih0Bf, bih0, gi, nullptr, nullptr, nullptr, H3, DIN);
    gru2<<<128, GRU_THR, GRU2_SMEM>>>(gi, Whh0, bhh0, init_hid, h0Bf, nullptr);

    // 4-5: layer 1
    gemm_hmma<64><<<dim3(H3 / 128, SB / 64), 256, 4 * (64 * 64 + 8192)>>>(
        h0Bf, wih1Bf, bih1, gi, nullptr, nullptr, nullptr, H3, HID);
    gru2<<<128, GRU_THR, GRU2_SMEM>>>(gi, Whh1, bhh1, init_hid + BATCH * HID, outBf, outseq);

    // 6: all head projections + scoreout + energy in one launch
    k_hso<<<(HSO_TOT + 255) / 256, 256>>>(outseq, Wfg, bfg, Wrg, brg, Wfs, bfs,
                                          ui_var, Wso, bso, i_features, word_ebd, Wfa, bfa);
    // 7: feature attention softmax
    k_scores<<<SB, 64>>>(user_vct, item_vct, if_mask);

    // 8: output transform fused: actBf = tanh(out @ Woo^T + boo + rg*score_out)
    gemm_hmma<64><<<dim3(HID / 128, SB / 64), 256, 4 * (64 * 64 + 8192)>>>(
        outBf, wooBf, boo, nullptr, actBf, rgP, soP, HID, HID);

    // 9: big vocab GEMM (bf16 logits)
    gemm_hmma<128><<<dim3(VOCAB / 128, SB / 128), 256, 4 * (128 * 64 + 8192)>>>(
        actBf, woutBf, bout, nullptr, logitsBf, nullptr, nullptr, VOCAB, HID);
    // 10: fused softmax/log/mix + scattered feature fix
    k_soft<<<SB, 1024, VOCAB * 2>>>(i_features, out);
}

// round 17
// speedup vs baseline: 1.0887x; 1.0748x over previous
#include <cuda_runtime.h>
#include <cuda_bf16.h>
#include <cstdint>

// ---------------- problem dims ----------------
#define SEQ    32
#define BATCH  32
#define SB     1024          // SEQ*BATCH
#define HID    512
#define H3     1536
#define DIN    512
#define VOCAB  32000
#define FEA    50

// ---------------- scratch (static device, no allocs) ----------------
__device__ __align__(16) __nv_bfloat16 g_embBf [SB * DIN];
__device__ __align__(16) __nv_bfloat16 g_Wih0Bf[H3 * DIN];
__device__ __align__(16) __nv_bfloat16 g_Wih1Bf[H3 * HID];
__device__ __align__(16) __nv_bfloat16 g_WooBf [HID * HID];
__device__ __align__(16) __nv_bfloat16 g_WoutBf[(size_t)VOCAB * HID];
__device__ __align__(16) float g_gi     [SB * H3];
__device__ __align__(16) __nv_bfloat16 g_h0Bf [SB * HID];
__device__ __align__(16) float g_outseq [SB * HID];
__device__ __align__(16) __nv_bfloat16 g_outBf[SB * HID];
__device__ __align__(16) __nv_bfloat16 g_actBf[SB * HID];
__device__ __align__(16) __nv_bfloat16 g_logitsBf[(size_t)SB * VOCAB];  // 65 MB
__device__ float g_fg[SB], g_rg[SB];
__device__ float g_fs[SB * 16];
__device__ float g_scoreout[BATCH * HID];
__device__ float g_energy[BATCH * FEA * 80];
__device__ float g_fattn[SB * FEA];

__device__ __forceinline__ float sigm(float x) { return 1.f / (1.f + expf(-x)); }

// packed dual-fp32 FMA (Blackwell f32x2 pipe; PTX-only form)
__device__ __forceinline__ unsigned long long fma2(unsigned long long a,
                                                   unsigned long long b,
                                                   unsigned long long c) {
    unsigned long long d;
    asm("fma.rn.f32x2 %0,%1,%2,%3;" : "=l"(d) : "l"(a), "l"(b), "l"(c));
    return d;
}
__device__ __forceinline__ float hsum2(unsigned long long v) {
    uint32_t lo, hi;
    asm("mov.b64 {%0,%1},%2;" : "=r"(lo), "=r"(hi) : "l"(v));
    return __uint_as_float(lo) + __uint_as_float(hi);
}
// bf16x2 (packed in u32) -> f32x2 (packed in u64)
__device__ __forceinline__ unsigned long long bf2f2(uint32_t v) {
    uint32_t lo = v << 16;
    uint32_t hi = v & 0xFFFF0000u;
    unsigned long long d;
    asm("mov.b64 %0,{%1,%2};" : "=l"(d) : "r"(lo), "r"(hi));
    return d;
}

// ---------------- HMMA bf16 GEMM: C[M,N] = A[M,K] @ B[N,K]^T + bias[N] ----
// BM=128: 8 warps 2m x 4n (128x128 tile). BM=64: 8 warps 1m x 8n (64x128).
// 4-stage cp.async pipeline, 1 __syncthreads per K-chunk, 2 CTAs/SM.
// smem rows of 32 bf16 (64B), chunk-XOR swizzle (conflict-free ldmatrix+fill).
// Cbf!=null -> bf16 out; RG!=null -> tanh(acc+bias+rg*so) bf16 out.
#define BK 32

__device__ __forceinline__ uint32_t sw_off(int row, int chunk) {
    return (uint32_t)(row * 64 + ((chunk ^ ((row >> 1) & 3)) << 4));
}

template<int BM>
__global__ __launch_bounds__(256, 2) void gemm_hmma(
    const __nv_bfloat16* __restrict__ A, const __nv_bfloat16* __restrict__ B,
    const float* __restrict__ bias, float* __restrict__ C,
    __nv_bfloat16* __restrict__ Cbf,
    const float* __restrict__ RG, const float* __restrict__ SO,
    int N, int K)
{
    constexpr int ASZ = BM * 64;         // A stage bytes
    constexpr int BSZ = 128 * 64;        // B stage bytes
    constexpr int SST = ASZ + BSZ;       // stage stride
    constexpr int NI  = (BM == 128) ? 4 : 2;
    extern __shared__ __align__(128) char gsm[];
    const int bm = blockIdx.y * BM, bn = blockIdx.x * 128;
    const int tid = threadIdx.x;
    const int warp = tid >> 5, lane = tid & 31;
    const int wm = (BM == 128) ? (warp & 1) * 64 : 0;
    const int wn = (BM == 128) ? (warp >> 1) * 32 : warp * 16;

    const uint32_t sBase = (uint32_t)__cvta_generic_to_shared(gsm);
    const int nk = K / BK;

    float acc[4][NI][4];
#pragma unroll
    for (int i = 0; i < 4; i++)
#pragma unroll
        for (int j = 0; j < NI; j++)
#pragma unroll
            for (int k = 0; k < 4; k++) acc[i][j][k] = 0.f;

    const int fr = tid >> 2, fc = tid & 3;
    auto issue = [&](int st, int kc) {
        if (kc < nk) {
            const __nv_bfloat16* Ag = A + (size_t)(bm + fr) * K + kc * BK + fc * 8;
            const __nv_bfloat16* Bg = B + (size_t)(bn + fr) * K + kc * BK + fc * 8;
            uint32_t aB = sBase + (uint32_t)(st * SST);
            uint32_t bB = aB + ASZ;
            asm volatile("cp.async.cg.shared.global [%0],[%1],16;"
                         :: "r"(aB + sw_off(fr, fc)), "l"(Ag));
            if (BM == 128)
                asm volatile("cp.async.cg.shared.global [%0],[%1],16;"
                             :: "r"(aB + sw_off(fr + 64, fc)), "l"(Ag + (size_t)64 * K));
            asm volatile("cp.async.cg.shared.global [%0],[%1],16;"
                         :: "r"(bB + sw_off(fr, fc)), "l"(Bg));
            asm volatile("cp.async.cg.shared.global [%0],[%1],16;"
                         :: "r"(bB + sw_off(fr + 64, fc)), "l"(Bg + (size_t)64 * K));
        }
        asm volatile("cp.async.commit_group;");
    };

    issue(0, 0); issue(1, 1); issue(2, 2);

    for (int kt = 0; kt < nk; kt++) {
        const int cur = kt & 3;
        asm volatile("cp.async.wait_group 2;");
        __syncthreads();
        issue((kt + 3) & 3, kt + 3);
        const uint32_t aC = sBase + (uint32_t)(cur * SST);
        const uint32_t bC = aC + ASZ;
#pragma unroll
        for (int kk = 0; kk < 2; kk++) {
            const int kb = kk * 2;
            uint32_t a[4][4], b[NI][2];
#pragma unroll
            for (int mi = 0; mi < 4; mi++) {
                int row = wm + mi * 16 + (lane & 15);
                uint32_t addr = aC + sw_off(row, kb + (lane >> 4));
                asm volatile("ldmatrix.sync.aligned.m8n8.x4.shared.b16 {%0,%1,%2,%3}, [%4];"
                             : "=r"(a[mi][0]), "=r"(a[mi][1]), "=r"(a[mi][2]), "=r"(a[mi][3])
                             : "r"(addr));
            }
#pragma unroll
            for (int ni = 0; ni < NI; ni++) {
                int row = wn + ni * 8 + (lane & 7);
                uint32_t addr = bC + sw_off(row, kb + ((lane >> 3) & 1));
                asm volatile("ldmatrix.sync.aligned.m8n8.x2.shared.b16 {%0,%1}, [%2];"
                             : "=r"(b[ni][0]), "=r"(b[ni][1]) : "r"(addr));
            }
#pragma unroll
            for (int mi = 0; mi < 4; mi++)
#pragma unroll
                for (int ni = 0; ni < NI; ni++) {
                    asm volatile(
                        "mma.sync.aligned.m16n8k16.row.col.f32.bf16.bf16.f32 "
                        "{%0,%1,%2,%3},{%4,%5,%6,%7},{%8,%9},{%0,%1,%2,%3};\n"
                        : "+f"(acc[mi][ni][0]), "+f"(acc[mi][ni][1]),
                          "+f"(acc[mi][ni][2]), "+f"(acc[mi][ni][3])
                        : "r"(a[mi][0]), "r"(a[mi][1]), "r"(a[mi][2]), "r"(a[mi][3]),
                          "r"(b[ni][0]), "r"(b[ni][1]));
                }
        }
    }

    const int g = lane >> 2, tg = lane & 3;
#pragma unroll
    for (int mi = 0; mi < 4; mi++)
#pragma unroll
        for (int ni = 0; ni < NI; ni++) {
            int row = bm + wm + mi * 16 + g;
            int col = bn + wn + ni * 8 + tg * 2;
            float b0 = bias[col], b1 = bias[col + 1];
            float v0 = acc[mi][ni][0] + b0, v1 = acc[mi][ni][1] + b1;
            float v2 = acc[mi][ni][2] + b0, v3 = acc[mi][ni][3] + b1;
            if (RG) {
                int ba = row & 31, bb = (row + 8) & 31;
                float r0 = RG[row], r1 = RG[row + 8];
                v0 = tanhf(v0 + r0 * SO[ba * HID + col]);
                v1 = tanhf(v1 + r0 * SO[ba * HID + col + 1]);
                v2 = tanhf(v2 + r1 * SO[bb * HID + col]);
                v3 = tanhf(v3 + r1 * SO[bb * HID + col + 1]);
            }
            if (Cbf) {
                *(__nv_bfloat162*)&Cbf[(size_t)row * N + col] = __floats2bfloat162_rn(v0, v1);
                *(__nv_bfloat162*)&Cbf[(size_t)(row + 8) * N + col] = __floats2bfloat162_rn(v2, v3);
            } else {
                C[(size_t)row * N + col]           = v0;
                C[(size_t)row * N + col + 1]       = v1;
                C[(size_t)(row + 8) * N + col]     = v2;
                C[(size_t)(row + 8) * N + col + 1] = v3;
            }
        }
}

// ---------------- GRU v5 (R14-proven): cluster-of-8, smem weights ----------
// 128 CTAs x 384 threads, clusters of 8. Cluster = one batch-pair.
// CTA rank = u-slice (64 units x 3 gates = 192 rows, 196KB bf16 in smem).
// Thread (g, kh): g = t%48 -> rows 4g..4g+3; kh = t/48 -> chunks kh*8..kh*8+7.
// h loads (broadcast) amortized over 4 rows.
// w slot rotation by row-GROUP: slot=(chunk+(row>>2))&63 -> lane-linear, CF.
// gh partials: float2 (batch0,batch1) at [kh][row], 8-way K reduction.
// mapa computed per step (hoisting regressed: indexed array spills to local).
#define GRU_THR       384
#define GRU2_W_BYTES  196608                        // 192 rows * 64 slots * 16B
#define GRU2_H_OFF    GRU2_W_BYTES                  // [2 phase][2 batch][512] f32
#define GRU2_GH_OFF   (GRU2_W_BYTES + 8192)         // [8 kh][192 row] float2
#define GRU2_SMEM     (GRU2_W_BYTES + 8192 + 12288) // 217088

__global__ __launch_bounds__(GRU_THR) __cluster_dims__(8, 1, 1)
void gru2(const float* __restrict__ gi, const float* __restrict__ Whh,
          const float* __restrict__ bhh, const float* __restrict__ h0,
          __nv_bfloat16* __restrict__ outBf, float* __restrict__ outF)
{
    extern __shared__ char sm[];
    __nv_bfloat16* w_s = (__nv_bfloat16*)sm;
    float*  h_s  = (float*)(sm + GRU2_H_OFF);
    float2* gh2  = (float2*)(sm + GRU2_GH_OFF);

    const int t = threadIdx.x;
    uint32_t rank;
    asm("mov.u32 %0, %%cluster_ctarank;" : "=r"(rank));
    const int uslc = (int)rank;
    const int b0 = (blockIdx.x >> 3) * 2;

    // weight fill: fp32 global -> bf16 smem, slot rotated by row-group
    for (int idx = t; idx < 192 * 64; idx += GRU_THR) {
        int row = idx >> 6, chunk = idx & 63;
        int G = (row >> 6) * HID + uslc * 64 + (row & 63);
        const float4* src = (const float4*)(Whh + (size_t)G * HID + chunk * 8);
        float4 v0 = src[0], v1 = src[1];
        int slot = (chunk + (row >> 2)) & 63;
        __nv_bfloat162* dst = (__nv_bfloat162*)(w_s + row * 512 + slot * 8);
        dst[0] = __floats2bfloat162_rn(v0.x, v0.y);
        dst[1] = __floats2bfloat162_rn(v0.z, v0.w);
        dst[2] = __floats2bfloat162_rn(v1.x, v1.y);
        dst[3] = __floats2bfloat162_rn(v1.z, v1.w);
    }
    for (int i = t; i < 2 * HID; i += GRU_THR) {
        int bb = i >> 9, k = i & 511;
        h_s[bb * 512 + k] = h0[(size_t)(b0 + bb) * HID + k];
    }
    const int g  = t % 48;          // row group: rows 4g..4g+3
    const int kh = t / 48;          // K-slice: chunks kh*8..kh*8+7
    const int r0w = 4 * g;
    float b_r = 0.f, b_z = 0.f, b_n = 0.f;
    int ul = 0, bb = 0, u = 0;
    if (t < 128) {
        ul = t >> 1; bb = t & 1; u = uslc * 64 + ul;
        b_r = bhh[u]; b_z = bhh[HID + u]; b_n = bhh[2 * HID + u];
    }
    __syncthreads();

    const uint4* wr0 = (const uint4*)(w_s + (r0w + 0) * 512);
    const uint4* wr1 = (const uint4*)(w_s + (r0w + 1) * 512);
    const uint4* wr2 = (const uint4*)(w_s + (r0w + 2) * 512);
    const uint4* wr3 = (const uint4*)(w_s + (r0w + 3) * 512);
    const int kh8 = kh * 8;

    for (int s = 0; s < SEQ; s++) {
        const int p = s & 1;
        float pir = 0.f, piz = 0.f, pin = 0.f;
        if (t < 128) {
            const float* gir = gi + (size_t)(s * BATCH + b0 + bb) * H3 + u;
            pir = gir[0]; piz = gir[HID]; pin = gir[2 * HID];
        }
        const float* hp = h_s + p * 1024;
        unsigned long long acc[4][2];
#pragma unroll
        for (int i = 0; i < 4; i++) { acc[i][0] = 0; acc[i][1] = 0; }
#pragma unroll
        for (int c = 0; c < 8; c++) {
            int ca = kh8 + c;
            int sl = (ca + g) & 63;
            uint4 wv0 = wr0[sl], wv1 = wr1[sl], wv2 = wr2[sl], wv3 = wr3[sl];
            int k0 = ca * 8;
            double2 xa = *(const double2*)(hp + k0);
            double2 xb = *(const double2*)(hp + k0 + 4);
            double2 ya = *(const double2*)(hp + 512 + k0);
            double2 yb = *(const double2*)(hp + 512 + k0 + 4);
            unsigned long long ha0 = __double_as_longlong(xa.x);
            unsigned long long ha1 = __double_as_longlong(xa.y);
            unsigned long long ha2 = __double_as_longlong(xb.x);
            unsigned long long ha3 = __double_as_longlong(xb.y);
            unsigned long long hb0 = __double_as_longlong(ya.x);
            unsigned long long hb1 = __double_as_longlong(ya.y);
            unsigned long long hb2 = __double_as_longlong(yb.x);
            unsigned long long hb3 = __double_as_longlong(yb.y);
#pragma unroll
            for (int i = 0; i < 4; i++) {
                uint4 wv = (i == 0) ? wv0 : (i == 1) ? wv1 : (i == 2) ? wv2 : wv3;
                unsigned long long w0 = bf2f2(wv.x);
                unsigned long long w1 = bf2f2(wv.y);
                unsigned long long w2 = bf2f2(wv.z);
                unsigned long long w3 = bf2f2(wv.w);
                acc[i][0] = fma2(w0, ha0, acc[i][0]);
                acc[i][0] = fma2(w1, ha1, acc[i][0]);
                acc[i][0] = fma2(w2, ha2, acc[i][0]);
                acc[i][0] = fma2(w3, ha3, acc[i][0]);
                acc[i][1] = fma2(w0, hb0, acc[i][1]);
                acc[i][1] = fma2(w1, hb1, acc[i][1]);
                acc[i][1] = fma2(w2, hb2, acc[i][1]);
                acc[i][1] = fma2(w3, hb3, acc[i][1]);
            }
        }
#pragma unroll
        for (int i = 0; i < 4; i++)
            gh2[kh * 192 + r0w + i] = make_float2(hsum2(acc[i][0]), hsum2(acc[i][1]));
        __syncthreads();
        if (t < 128) {
            float ghr = b_r, ghz = b_z, ghn = b_n;
#pragma unroll
            for (int k2 = 0; k2 < 8; k2++) {
                float2 vr = gh2[k2 * 192 + ul];
                float2 vz = gh2[k2 * 192 + 64 + ul];
                float2 vn = gh2[k2 * 192 + 128 + ul];
                ghr += bb ? vr.y : vr.x;
                ghz += bb ? vz.y : vz.x;
                ghn += bb ? vn.y : vn.x;
            }
            float rr = sigm(pir + ghr);
            float zz = sigm(piz + ghz);
            float nn = tanhf(pin + rr * ghn);
            float h2 = (1.f - zz) * nn + zz * hp[bb * 512 + u];
            size_t orow = (size_t)(s * BATCH + b0 + bb) * HID + u;
            outBf[orow] = __float2bfloat16(h2);
            if (outF) outF[orow] = h2;
            int wofs = (p ^ 1) * 1024 + bb * 512 + u;
            h_s[wofs] = h2;
            uint32_t laddr = (uint32_t)__cvta_generic_to_shared(&h_s[wofs]);
#pragma unroll
            for (int pr = 0; pr < 8; pr++) {
                if (pr == uslc) continue;
                uint32_t raddr;
                asm volatile("mapa.shared::cluster.u32 %0, %1, %2;"
                             : "=r"(raddr) : "r"(laddr), "r"(pr));
                asm volatile("st.shared::cluster.f32 [%0], %1;"
                             :: "r"(raddr), "f"(h2) : "memory");
            }
        }
        asm volatile("barrier.cluster.arrive.aligned;" ::: "memory");
        asm volatile("barrier.cluster.wait.aligned;" ::: "memory");
    }
}

// ---------------- small kernels ----------------
#define N_WOUT4 (VOCAB * HID / 4)
#define N_WIH04 (H3 * DIN / 4)
#define N_WIH14 (H3 * HID / 4)
#define N_WOO4  (HID * HID / 4)
#define N_CVT_TOT (N_WOUT4 + N_WIH04 + N_WIH14 + N_WOO4)

__global__ void k_cvtall(const float* __restrict__ s0, __nv_bfloat16* __restrict__ d0,
                         const float* __restrict__ s1, __nv_bfloat16* __restrict__ d1,
                         const float* __restrict__ s2, __nv_bfloat16* __restrict__ d2,
                         const float* __restrict__ s3, __nv_bfloat16* __restrict__ d3) {
    int i = blockIdx.x * blockDim.x + threadIdx.x;
    const float* s; __nv_bfloat16* d; int off;
    if (i < N_WOUT4)                               { s = s0; d = d0; off = i; }
    else if (i < N_WOUT4 + N_WIH04)                { s = s1; d = d1; off = i - N_WOUT4; }
    else if (i < N_WOUT4 + N_WIH04 + N_WIH14)      { s = s2; d = d2; off = i - N_WOUT4 - N_WIH04; }
    else if (i < N_CVT_TOT)                        { s = s3; d = d3; off = i - N_WOUT4 - N_WIH04 - N_WIH14; }
    else return;
    float4 v = ((const float4*)s)[off];
    __nv_bfloat162* o = (__nv_bfloat162*)d + 2 * off;
    o[0] = __floats2bfloat162_rn(v.x, v.y);
    o[1] = __floats2bfloat162_rn(v.z, v.w);
}

__global__ void k_emb(const int* __restrict__ seq, const float* __restrict__ word_ebd) {
    int t = blockIdx.x * blockDim.x + threadIdx.x;
    if (t >= SB * (DIN / 4)) return;
    int row = t / (DIN / 4), k = t % (DIN / 4);
    float4 v = ((const float4*)(word_ebd + (size_t)seq[row] * DIN))[k];
    __nv_bfloat162* o = (__nv_bfloat162*)(g_embBf + row * DIN) + 2 * k;
    o[0] = __floats2bfloat162_rn(v.x, v.y);
    o[1] = __floats2bfloat162_rn(v.z, v.w);
}

__global__ void k_heads(const float* __restrict__ outseq,
                        const float* Wfg, const float* bfg,
                        const float* Wrg, const float* brg,
                        const float* Wfs, const float* bfs)
{
    int t = blockIdx.x * blockDim.x + threadIdx.x;
    if (t >= SB * 18) return;
    int row = t / 18, which = t % 18;
    const float* x = outseq + (size_t)row * HID;
    const float* w;
    float bias;
    if (which == 0)      { w = Wfg;                          bias = bfg[0]; }
    else if (which == 1) { w = Wrg;                          bias = brg[0]; }
    else                 { w = Wfs + (size_t)(which - 2) * HID; bias = bfs[which - 2]; }
    float s = 0.f;
#pragma unroll 4
    for (int k = 0; k < HID; k++) s += x[k] * w[k];
    s += bias;
    if (which == 0)      g_fg[row] = sigm(s);
    else if (which == 1) g_rg[row] = sigm(s);
    else                 g_fs[row * 16 + which - 2] = s;
}

__global__ void k_scoreout(const float* __restrict__ ui_var,
                           const float* __restrict__ Wso, const float* __restrict__ bso) {
    int t = blockIdx.x * blockDim.x + threadIdx.x;
    if (t >= BATCH * HID) return;
    int b = t / HID, u = t % HID;
    float s = 0.f;
#pragma unroll
    for (int k = 0; k < 32; k++) s += ui_var[b * 32 + k] * Wso[u * 32 + k];
    g_scoreout[t] = s + bso[u];
}

__global__ void k_energy(const int* __restrict__ i_features, const float* __restrict__ word_ebd,
                         const float* __restrict__ Wfa, const float* __restrict__ bfa) {
    int t = blockIdx.x * blockDim.x + threadIdx.x;
    if (t >= BATCH * FEA * 80) return;
    int j = t % 80, bf = t / 80;
    const float* x = word_ebd + (size_t)i_features[bf] * DIN;
    const float* w = Wfa + (size_t)j * DIN;
    float s = 0.f;
#pragma unroll 4
    for (int k = 0; k < DIN; k++) s += x[k] * w[k];
    g_energy[t] = s + bfa[j];
}

__global__ void k_scores(const float* __restrict__ user, const float* __restrict__ item,
                         const int* __restrict__ mask) {
    int row = blockIdx.x;          // s*32+b
    int b = row & 31;
    __shared__ float sc[FEA];
    __shared__ float red[2];
    int f = threadIdx.x;
    if (f < FEA) {
        const float* e = g_energy + (size_t)(b * FEA + f) * 80;
        float s = 0.f;
#pragma unroll
        for (int k = 0; k < 16; k++) s += g_fs[row * 16 + k] * e[k];
#pragma unroll
        for (int k = 0; k < 32; k++) s += user[b * 32 + k] * e[16 + k];
#pragma unroll
        for (int k = 0; k < 32; k++) s += item[b * 32 + k] * e[48 + k];
        if (mask[b * FEA + f] == 0) s = -1e9f;
        sc[f] = s;
    }
    __syncthreads();
    if (threadIdx.x == 0) {
        float m = -1e30f;
        for (int i = 0; i < FEA; i++) m = fmaxf(m, sc[i]);
        float sum = 0.f;
        for (int i = 0; i < FEA; i++) sum += expf(sc[i] - m);
        red[0] = m; red[1] = sum;
    }
    __syncthreads();
    if (f < FEA) g_fattn[row * FEA + f] = expf(sc[f] - red[0]) / red[1];
}

// fused: rowsum(exp) + log-mix + scattered feature fix, bf16 logits in smem
__global__ __launch_bounds__(1024) void k_soft(const int* __restrict__ i_features,
                                               float* __restrict__ out) {
    extern __shared__ __align__(16) __nv_bfloat16 lsb[];  // VOCAB bf16 = 64000 B
    __shared__ float red[32];
    __shared__ float cb_s, rs_s;
    const int row = blockIdx.x, t = threadIdx.x;
    const uint4* src = (const uint4*)(g_logitsBf + (size_t)row * VOCAB);
    float s = 0.f;
    for (int i = t; i < VOCAB / 8; i += 1024) {
        uint4 l = src[i];
        ((uint4*)lsb)[i] = l;
        float2 p0 = __bfloat1622float2(*(__nv_bfloat162*)&l.x);
        float2 p1 = __bfloat1622float2(*(__nv_bfloat162*)&l.y);
        float2 p2 = __bfloat1622float2(*(__nv_bfloat162*)&l.z);
        float2 p3 = __bfloat1622float2(*(__nv_bfloat162*)&l.w);
        s += __expf(p0.x) + __expf(p0.y) + __expf(p1.x) + __expf(p1.y)
           + __expf(p2.x) + __expf(p2.y) + __expf(p3.x) + __expf(p3.y);
    }
#pragma unroll
    for (int o = 16; o > 0; o >>= 1) s += __shfl_down_sync(~0u, s, o);
    if ((t & 31) == 0) red[t >> 5] = s;
    __syncthreads();
    if (t < 32) {
        float v = red[t];
#pragma unroll
        for (int o = 16; o > 0; o >>= 1) v += __shfl_down_sync(~0u, v, o);
        if (t == 0) {
            rs_s = v;
            cb_s = logf(v) - logf(1.f - g_fg[row]);
        }
    }
    __syncthreads();
    const float c = cb_s;
    float4* dst = (float4*)(out + (size_t)row * VOCAB);
    for (int i = t; i < VOCAB / 8; i += 1024) {
        uint4 l = ((const uint4*)lsb)[i];
        float2 p0 = __bfloat1622float2(*(__nv_bfloat162*)&l.x);
        float2 p1 = __bfloat1622float2(*(__nv_bfloat162*)&l.y);
        float2 p2 = __bfloat1622float2(*(__nv_bfloat162*)&l.z);
        float2 p3 = __bfloat1622float2(*(__nv_bfloat162*)&l.w);
        float4 o0, o1;
        o0.x = p0.x - c; o0.y = p0.y - c; o0.z = p1.x - c; o0.w = p1.y - c;
        o1.x = p2.x - c; o1.y = p2.y - c; o1.z = p3.x - c; o1.w = p3.y - c;
        dst[2 * i]     = o0;
        dst[2 * i + 1] = o1;
    }
    __syncthreads();
    if (t < FEA) {
        int b = row & 31;
        int v = i_features[b * FEA + t];
        float logit = __bfloat162float(lsb[v]);
        float fg = g_fg[row];
        float p = __expf(logit) / rs_s;
        out[(size_t)row * VOCAB + v] = logf((1.f - fg) * p + fg * g_fattn[row * FEA + t]);
    }
}

// ---------------- launch ----------------
extern "C" void kernel_launch(void* const* d_in, const int* in_sizes, int n_in,
                              void* d_out, int out_size)
{
    const int*   input_seq  = (const int*)d_in[0];
    const float* init_hid   = (const float*)d_in[1];
    const float* user_vct   = (const float*)d_in[2];
    const float* item_vct   = (const float*)d_in[3];
    const float* ui_var     = (const float*)d_in[4];
    const int*   i_features = (const int*)d_in[5];
    const int*   if_mask    = (const int*)d_in[6];    // bool -> int32 in harness
    const float* word_ebd = (const float*)d_in[7];
    const float* Wih0 = (const float*)d_in[8];  const float* Whh0 = (const float*)d_in[9];
    const float* bih0 = (const float*)d_in[10]; const float* bhh0 = (const float*)d_in[11];
    const float* Wih1 = (const float*)d_in[12]; const float* Whh1 = (const float*)d_in[13];
    const float* bih1 = (const float*)d_in[14]; const float* bhh1 = (const float*)d_in[15];
    const float* Wout = (const float*)d_in[16]; const float* bout = (const float*)d_in[17];
    const float* Wrg  = (const float*)d_in[18]; const float* brg  = (const float*)d_in[19];
    const float* Wso  = (const float*)d_in[20]; const float* bso  = (const float*)d_in[21];
    const float* Woo  = (const float*)d_in[22]; const float* boo  = (const float*)d_in[23];
    const float* Wfg  = (const float*)d_in[24]; const float* bfg  = (const float*)d_in[25];
    const float* Wfs  = (const float*)d_in[26]; const float* bfs  = (const float*)d_in[27];
    const float* Wfa  = (const float*)d_in[28]; const float* bfa  = (const float*)d_in[29];
    float* out = (float*)d_out;

    __nv_bfloat16 *embBf, *wih0Bf, *wih1Bf, *wooBf, *woutBf, *h0Bf, *outBf, *actBf, *logitsBf;
    float *gi, *outseq, *rgP, *soP;
    cudaGetSymbolAddress((void**)&embBf,  g_embBf);
    cudaGetSymbolAddress((void**)&wih0Bf, g_Wih0Bf);
    cudaGetSymbolAddress((void**)&wih1Bf, g_Wih1Bf);
    cudaGetSymbolAddress((void**)&wooBf,  g_WooBf);
    cudaGetSymbolAddress((void**)&woutBf, g_WoutBf);
    cudaGetSymbolAddress((void**)&h0Bf,   g_h0Bf);
    cudaGetSymbolAddress((void**)&outBf,  g_outBf);
    cudaGetSymbolAddress((void**)&actBf,  g_actBf);
    cudaGetSymbolAddress((void**)&logitsBf, g_logitsBf);
    cudaGetSymbolAddress((void**)&gi,     g_gi);
    cudaGetSymbolAddress((void**)&outseq, g_outseq);
    cudaGetSymbolAddress((void**)&rgP,    g_rg);
    cudaGetSymbolAddress((void**)&soP,    g_scoreout);

    cudaFuncSetAttribute(gemm_hmma<128>, cudaFuncAttributeMaxDynamicSharedMemorySize, 4 * (128 * 64 + 8192));
    cudaFuncSetAttribute(gemm_hmma<64>,  cudaFuncAttributeMaxDynamicSharedMemorySize, 4 * (64 * 64 + 8192));
    cudaFuncSetAttribute(gru2,   cudaFuncAttributeMaxDynamicSharedMemorySize, GRU2_SMEM);
    cudaFuncSetAttribute(k_soft, cudaFuncAttributeMaxDynamicSharedMemorySize, VOCAB * 2);

    // 0: all weight conversions in one launch
    k_cvtall<<<(N_CVT_TOT + 255) / 256, 256>>>(Wout, woutBf, Wih0, wih0Bf,
                                               Wih1, wih1Bf, Woo, wooBf);
    // 1: embedding gather
    k_emb<<<(SB * DIN / 4 + 255) / 256, 256>>>(input_seq, word_ebd);

    // 2-3: layer 0
    gemm_hmma<64><<<dim3(H3 / 128, SB / 64), 256, 4 * (64 * 64 + 8192)>>>(
        embBf, wih0Bf, bih0, gi, nullptr, nullptr, nullptr, H3, DIN);
    gru2<<<128, GRU_THR, GRU2_SMEM>>>(gi, Whh0, bhh0, init_hid, h0Bf, nullptr);

    // 4-5: layer 1
    gemm_hmma<64><<<dim3(H3 / 128, SB / 64), 256, 4 * (64 * 64 + 8192)>>>(
        h0Bf, wih1Bf, bih1, gi, nullptr, nullptr, nullptr, H3, HID);
    gru2<<<128, GRU_THR, GRU2_SMEM>>>(gi, Whh1, bhh1, init_hid + BATCH * HID, outBf, outseq);

    // heads on GRU output (pre-transform)
    k_heads<<<(SB * 18 + 255) / 256, 256>>>(outseq, Wfg, bfg, Wrg, brg, Wfs, bfs);
    k_scoreout<<<(BATCH * HID + 255) / 256, 256>>>(ui_var, Wso, bso);
    k_energy<<<(BATCH * FEA * 80 + 255) / 256, 256>>>(i_features, word_ebd, Wfa, bfa);
    k_scores<<<SB, 64>>>(user_vct, item_vct, if_mask);

    // output transform fused: actBf = tanh(out @ Woo^T + boo + rg*score_out)
    gemm_hmma<64><<<dim3(HID / 128, SB / 64), 256, 4 * (64 * 64 + 8192)>>>(
        outBf, wooBf, boo, nullptr, actBf, rgP, soP, HID, HID);

    // big vocab GEMM (bf16 logits) + fused softmax/log/mix + feature fix
    gemm_hmma<128><<<dim3(VOCAB / 128, SB / 128), 256, 4 * (128 * 64 + 8192)>>>(
        actBf, woutBf, bout, nullptr, logitsBf, nullptr, nullptr, VOCAB, HID);
    k_soft<<<SB, 1024, VOCAB * 2>>>(i_features, out);
}